// round 15
// baseline (speedup 1.0000x reference)
#include <cuda_runtime.h>
#include <cuda_fp16.h>
#include <cstdint>

#define N_NODES 20000
#define N_EDGES 320000
#define ET      (N_EDGES + N_NODES)   // 340000
#define GCN_IN  256
#define C1      128
#define H1      5
#define F1      (H1*C1)               // 640
#define C2      128
#define H2      3
#define F2      (H2*C2)               // 384
#define N_BBOX  4096
#define NB_SCAN ((N_NODES + 1023) / 1024)   // 20
#define MAXDEG  256                   // degree cap for smem softmax

// ---------------- scratch ---------------------------------------------------
__device__ int    g_is64;
__device__ int    g_cnt[N_NODES];     // zeroed by k_agg1 after use
__device__ int    g_cur[N_NODES];     // zeroed by k_agg1 after use
__device__ int    g_off[N_NODES + 1];
__device__ int    g_src[ET];
__device__ int    g_flag;             // scan chaining flag (self-resetting)
__device__ int    g_carry;            // scan carry (self-resetting)
__device__ __half g_xh[(size_t)N_NODES * GCN_IN];
__device__ __half g_w1h[F1 * GCN_IN];
__device__ __half g_w2h[F2 * F1];
__device__ __half g_h1h[(size_t)N_NODES * F1];
__device__ __half g_h2h[(size_t)N_NODES * F2];
__device__ __half g_o1h[(size_t)N_NODES * F1];
__device__ float  g_as1[N_NODES * H1];
__device__ float  g_ad1[N_NODES * H1];
__device__ float  g_as2[N_NODES * H2];
__device__ float  g_ad2[N_NODES * H2];

__device__ __forceinline__ float leaky(float x, float s) {
    return x >= 0.f ? x : s * x;
}
__device__ __forceinline__ int load_idx(const void* p, long long i) {
    return g_is64 ? (int)((const long long*)p)[i] : ((const int*)p)[i];
}
__device__ __forceinline__ void ldm_x4(uint32_t (&r)[4], uint32_t addr) {
    asm volatile("ldmatrix.sync.aligned.m8n8.x4.shared.b16 {%0,%1,%2,%3}, [%4];"
                 : "=r"(r[0]), "=r"(r[1]), "=r"(r[2]), "=r"(r[3]) : "r"(addr));
}

// ---------------- dtype sniff (1 warp) --------------------------------------
__global__ void k_detect(const void* ei) {
    if (threadIdx.x == 0) {
        const int* p = (const int*)ei;
        int nz = 0;
        #pragma unroll
        for (int j = 0; j < 64; j++) nz |= p[2 * j + 1];
        g_is64 = (nz == 0) ? 1 : 0;
    }
}

// ---------------- fp32 -> fp16 convert --------------------------------------
__global__ void k_tohalf(const float* __restrict__ in, __half* __restrict__ out, int n8) {
    int i = blockIdx.x * blockDim.x + threadIdx.x;
    if (i >= n8) return;
    float4 v0 = reinterpret_cast<const float4*>(in)[2 * i];
    float4 v1 = reinterpret_cast<const float4*>(in)[2 * i + 1];
    __half2 h[4];
    h[0] = __floats2half2_rn(v0.x, v0.y);
    h[1] = __floats2half2_rn(v0.z, v0.w);
    h[2] = __floats2half2_rn(v1.x, v1.y);
    h[3] = __floats2half2_rn(v1.z, v1.w);
    reinterpret_cast<uint4*>(out)[i] = *reinterpret_cast<uint4*>(h);
}

// ---------------- transpose -> fp16: W[K][N] -> Wt[N][K] --------------------
__global__ void k_transpose_h(const float* __restrict__ in, __half* __restrict__ out,
                              int K, int N) {
    __shared__ float tile[32][33];
    int n0 = blockIdx.x * 32, k0 = blockIdx.y * 32;
    int tx = threadIdx.x, ty = threadIdx.y;
    #pragma unroll
    for (int j = 0; j < 32; j += 8)
        tile[ty + j][tx] = in[(size_t)(k0 + ty + j) * N + n0 + tx];
    __syncthreads();
    #pragma unroll
    for (int j = 0; j < 32; j += 8)
        out[(size_t)(n0 + ty + j) * K + k0 + tx] = __float2half(tile[tx][ty + j]);
}

// ---------------- CSR build -------------------------------------------------
__global__ void k_hist(const void* __restrict__ ei) {
    int e = blockIdx.x * blockDim.x + threadIdx.x;
    if (e >= ET) return;
    int dst = (e < N_EDGES) ? load_idx(ei, (long long)N_EDGES + e) : (e - N_EDGES);
    atomicAdd(&g_cnt[dst], 1);
}

// single-kernel exclusive scan via sequential block chaining (20 blocks,
// all co-resident). Self-resets g_flag/g_carry for next graph replay.
__global__ void k_scan_fused() {
    __shared__ int ws[32];
    __shared__ int carry_sh;
    int tid = threadIdx.x, lane = tid & 31, wid = tid >> 5;
    int b = blockIdx.x;
    int i = b * 1024 + tid;
    int v = (i < N_NODES) ? g_cnt[i] : 0;
    int x = v;
    #pragma unroll
    for (int o = 1; o < 32; o <<= 1) {
        int y = __shfl_up_sync(~0u, x, o);
        if (lane >= o) x += y;
    }
    if (lane == 31) ws[wid] = x;
    __syncthreads();
    if (wid == 0) {
        int w = ws[lane];
        #pragma unroll
        for (int o = 1; o < 32; o <<= 1) {
            int y = __shfl_up_sync(~0u, w, o);
            if (lane >= o) w += y;
        }
        ws[lane] = w;
    }
    __syncthreads();
    int incl = x + (wid > 0 ? ws[wid - 1] : 0);
    int total = ws[31];

    // wait for predecessor's carry
    if (tid == 0) {
        volatile int* fp = &g_flag;
        while (*fp != b) { }
        __threadfence();
        carry_sh = g_carry;
    }
    __syncthreads();
    int c = carry_sh;
    if (i < N_NODES) g_off[i + 1] = c + incl;
    if (i == 0) g_off[0] = 0;
    if (tid == 0) {
        if (b == NB_SCAN - 1) {
            // last block: reset chaining state for next replay
            g_carry = 0;
            __threadfence();
            g_flag = 0;
        } else {
            g_carry = c + total;
            __threadfence();
            g_flag = b + 1;
        }
    }
}

__global__ void k_scatter(const void* __restrict__ ei) {
    int e = blockIdx.x * blockDim.x + threadIdx.x;
    if (e >= ET) return;
    int src, dst;
    if (e < N_EDGES) {
        src = load_idx(ei, e);
        dst = load_idx(ei, (long long)N_EDGES + e);
    } else {
        src = dst = e - N_EDGES;
    }
    int p = g_off[dst] + atomicAdd(&g_cur[dst], 1);
    g_src[p] = src;
}

// ---------------- FP16 GEMM (m16n8k16) — high occupancy ---------------------
#define GBM 64
#define GBN 128
#define GBK 32
#define SAh 40
#define STG 3
#define A_STAGE_H (GBM * SAh)
#define B_STAGE_H (GBN * SAh)
#define GEMM_SMEM (STG * (A_STAGE_H + B_STAGE_H) * 2)   // 46080 B

template<int MODE>
__global__ void __launch_bounds__(256, 3)
gemm_f16(const float* __restrict__ asrc, const float* __restrict__ adst) {
    const int M = N_NODES;
    const int K = (MODE == 0) ? GCN_IN : F1;
    const int N = (MODE == 0) ? F1 : F2;
    const int H = (MODE == 0) ? H1 : H2;
    const __half* A  = (MODE == 0) ? (const __half*)g_xh  : (const __half*)g_o1h;
    const __half* Bt = (MODE == 0) ? (const __half*)g_w1h : (const __half*)g_w2h;
    __half* Ch = (MODE == 0) ? g_h1h : g_h2h;
    float* oas = (MODE == 0) ? g_as1 : g_as2;
    float* oad = (MODE == 0) ? g_ad1 : g_ad2;

    extern __shared__ __half smemh[];
    __half* As = smemh;
    __half* Bs = smemh + STG * A_STAGE_H;
    __shared__ float red_s[4][GBM], red_d[4][GBM];

    int tid = threadIdx.x, lane = tid & 31, warp = tid >> 5;
    int warp_m = (warp & 1) * 32;
    int warp_n = (warp >> 1) * 32;
    int ngrp = warp >> 1;
    int head = blockIdx.x;
    int rb = blockIdx.y * GBM, cb = head * GBN;
    int grp = lane >> 2, sub = lane & 3;

    uint32_t sAb = (uint32_t)__cvta_generic_to_shared(As);
    uint32_t sBb = (uint32_t)__cvta_generic_to_shared(Bs);
    int mi = lane >> 3, r = lane & 7;
    uint32_t aoff = sAb + (((warp_m + r + 8 * (mi & 1)) * SAh + 8 * (mi >> 1)) << 1);
    uint32_t boff = sBb + (((warp_n + r + 8 * (mi >> 1)) * SAh + 8 * (mi & 1)) << 1);

    float acc[2][4][4];
    #pragma unroll
    for (int i = 0; i < 2; i++)
        #pragma unroll
        for (int j = 0; j < 4; j++)
            #pragma unroll
            for (int q = 0; q < 4; q++) acc[i][j][q] = 0.f;

    auto copy_tile = [&](int t, int buf) {
        int k0 = t * GBK;
        __half* Ab = As + buf * A_STAGE_H;
        __half* Bb = Bs + buf * B_STAGE_H;
        #pragma unroll
        for (int p = 0; p < 3; p++) {
            int c = p * 256 + tid;
            if (c < 256) {
                int row = c >> 2, col = (c & 3) * 8;
                const __half* src = A + (size_t)(rb + row) * K + k0 + col;
                uint32_t dst = (uint32_t)__cvta_generic_to_shared(&Ab[row * SAh + col]);
                int sz = (rb + row < M) ? 16 : 0;
                asm volatile("cp.async.cg.shared.global [%0], [%1], 16, %2;\n"
                             :: "r"(dst), "l"(src), "r"(sz));
            } else {
                int cB = c - 256;
                int row = cB >> 2, col = (cB & 3) * 8;
                const __half* src = Bt + (size_t)(cb + row) * K + k0 + col;
                uint32_t dst = (uint32_t)__cvta_generic_to_shared(&Bb[row * SAh + col]);
                asm volatile("cp.async.cg.shared.global [%0], [%1], 16;\n"
                             :: "r"(dst), "l"(src));
            }
        }
        asm volatile("cp.async.commit_group;\n" ::: "memory");
    };

    const int T = K / GBK;
    copy_tile(0, 0);
    copy_tile(1, 1);

    for (int t = 0; t < T; t++) {
        if (t < T - 1)
            asm volatile("cp.async.wait_group 1;\n" ::: "memory");
        else
            asm volatile("cp.async.wait_group 0;\n" ::: "memory");
        __syncthreads();
        if (t + 2 < T) copy_tile(t + 2, (t + 2) % STG);

        int buf = t % STG;
        uint32_t aB = aoff + buf * (A_STAGE_H * 2);
        uint32_t bB = boff + buf * (B_STAGE_H * 2);

        #pragma unroll
        for (int ks = 0; ks < 2; ks++) {
            uint32_t a0[4], a1[4];
            ldm_x4(a0, aB + ks * 32);
            ldm_x4(a1, aB + ks * 32 + 16 * SAh * 2);
            #pragma unroll
            for (int nt2 = 0; nt2 < 2; nt2++) {
                uint32_t b[4];
                ldm_x4(b, bB + ks * 32 + nt2 * (16 * SAh * 2));
                #pragma unroll
                for (int mt = 0; mt < 2; mt++) {
                    const uint32_t* a = (mt == 0) ? a0 : a1;
                    asm volatile(
                        "mma.sync.aligned.m16n8k16.row.col.f32.f16.f16.f32 "
                        "{%0,%1,%2,%3}, {%4,%5,%6,%7}, {%8,%9}, {%0,%1,%2,%3};"
                        : "+f"(acc[mt][2 * nt2][0]), "+f"(acc[mt][2 * nt2][1]),
                          "+f"(acc[mt][2 * nt2][2]), "+f"(acc[mt][2 * nt2][3])
                        : "r"(a[0]), "r"(a[1]), "r"(a[2]), "r"(a[3]),
                          "r"(b[0]), "r"(b[1]));
                    asm volatile(
                        "mma.sync.aligned.m16n8k16.row.col.f32.f16.f16.f32 "
                        "{%0,%1,%2,%3}, {%4,%5,%6,%7}, {%8,%9}, {%0,%1,%2,%3};"
                        : "+f"(acc[mt][2 * nt2 + 1][0]), "+f"(acc[mt][2 * nt2 + 1][1]),
                          "+f"(acc[mt][2 * nt2 + 1][2]), "+f"(acc[mt][2 * nt2 + 1][3])
                        : "r"(a[0]), "r"(a[1]), "r"(a[2]), "r"(a[3]),
                          "r"(b[2]), "r"(b[3]));
                }
            }
        }
    }

    // ---- store C as fp16 ----
    #pragma unroll
    for (int mt = 0; mt < 2; mt++) {
        int r0 = rb + warp_m + mt * 16 + grp;
        #pragma unroll
        for (int nt = 0; nt < 4; nt++) {
            int c0 = cb + warp_n + nt * 8 + 2 * sub;
            if (r0 < M)
                *reinterpret_cast<__half2*>(Ch + (size_t)r0 * N + c0) =
                    __floats2half2_rn(acc[mt][nt][0], acc[mt][nt][1]);
            if (r0 + 8 < M)
                *reinterpret_cast<__half2*>(Ch + (size_t)(r0 + 8) * N + c0) =
                    __floats2half2_rn(acc[mt][nt][2], acc[mt][nt][3]);
        }
    }

    // ---- fused attention dots ----
    float ps[2][2] = {{0.f, 0.f}, {0.f, 0.f}};
    float pd[2][2] = {{0.f, 0.f}, {0.f, 0.f}};
    #pragma unroll
    for (int nt = 0; nt < 4; nt++) {
        int cc = warp_n + nt * 8 + 2 * sub;
        float s0 = asrc[head * 128 + cc],     d0 = adst[head * 128 + cc];
        float s1 = asrc[head * 128 + cc + 1], d1 = adst[head * 128 + cc + 1];
        #pragma unroll
        for (int mt = 0; mt < 2; mt++) {
            ps[mt][0] += acc[mt][nt][0] * s0 + acc[mt][nt][1] * s1;
            pd[mt][0] += acc[mt][nt][0] * d0 + acc[mt][nt][1] * d1;
            ps[mt][1] += acc[mt][nt][2] * s0 + acc[mt][nt][3] * s1;
            pd[mt][1] += acc[mt][nt][2] * d0 + acc[mt][nt][3] * d1;
        }
    }
    #pragma unroll
    for (int mt = 0; mt < 2; mt++)
        #pragma unroll
        for (int hf = 0; hf < 2; hf++) {
            #pragma unroll
            for (int o = 1; o < 4; o <<= 1) {
                ps[mt][hf] += __shfl_xor_sync(~0u, ps[mt][hf], o);
                pd[mt][hf] += __shfl_xor_sync(~0u, pd[mt][hf], o);
            }
        }
    if (sub == 0) {
        #pragma unroll
        for (int mt = 0; mt < 2; mt++)
            #pragma unroll
            for (int hf = 0; hf < 2; hf++) {
                int lr = warp_m + mt * 16 + hf * 8 + grp;
                red_s[ngrp][lr] = ps[mt][hf];
                red_d[ngrp][lr] = pd[mt][hf];
            }
    }
    __syncthreads();
    if (ngrp == 0 && sub == 0) {
        #pragma unroll
        for (int mt = 0; mt < 2; mt++)
            #pragma unroll
            for (int hf = 0; hf < 2; hf++) {
                int lr = warp_m + mt * 16 + hf * 8 + grp;
                int rr = rb + lr;
                if (rr < M) {
                    float ts = red_s[0][lr] + red_s[1][lr] + red_s[2][lr] + red_s[3][lr];
                    float td = red_d[0][lr] + red_d[1][lr] + red_d[2][lr] + red_d[3][lr];
                    oas[rr * H + head] = ts;
                    oad[rr * H + head] = td;
                }
            }
    }
}

// ---------------- fused softmax + layer-1 aggregation -----------------------
__global__ void k_agg1(const float* __restrict__ b1) {
    __shared__ float s_alpha[MAXDEG][H1];
    int n = blockIdx.x;
    int head = threadIdx.x >> 5;
    int lane = threadIdx.x & 31;
    int c = head * 128 + lane * 4;
    int beg = g_off[n], end = g_off[n + 1];
    int deg = end - beg;
    float adv = g_ad1[n * H1 + head];

    float m = -1e30f;
    for (int i = beg + lane; i < end; i += 32) {
        int s = g_src[i];
        float e = leaky(g_as1[s * H1 + head] + adv, 0.2f);
        int idx = i - beg;
        if (idx < MAXDEG) s_alpha[idx][head] = e;
        m = fmaxf(m, e);
    }
    #pragma unroll
    for (int o = 16; o; o >>= 1) m = fmaxf(m, __shfl_xor_sync(~0u, m, o));
    __syncwarp();

    float sum = 0.f;
    for (int idx = lane; idx < deg; idx += 32) {
        float ex;
        if (idx < MAXDEG) {
            ex = expf(s_alpha[idx][head] - m);
            s_alpha[idx][head] = ex;
        } else {
            int s = g_src[beg + idx];
            ex = expf(leaky(g_as1[s * H1 + head] + adv, 0.2f) - m);
        }
        sum += ex;
    }
    #pragma unroll
    for (int o = 16; o; o >>= 1) sum += __shfl_xor_sync(~0u, sum, o);
    float rinv = 1.f / (sum + 1e-16f);
    __syncwarp();

    float4 acc = make_float4(0.f, 0.f, 0.f, 0.f);
    int i = beg;
    for (; i + 4 <= end && (i - beg) + 4 <= MAXDEG; i += 4) {
        int idx = i - beg;
        int s0 = g_src[i], s1 = g_src[i + 1], s2 = g_src[i + 2], s3 = g_src[i + 3];
        float a0 = s_alpha[idx][head];
        float a1 = s_alpha[idx + 1][head];
        float a2 = s_alpha[idx + 2][head];
        float a3 = s_alpha[idx + 3][head];
        uint2 u0 = *reinterpret_cast<const uint2*>(g_h1h + (size_t)s0 * F1 + c);
        uint2 u1 = *reinterpret_cast<const uint2*>(g_h1h + (size_t)s1 * F1 + c);
        uint2 u2 = *reinterpret_cast<const uint2*>(g_h1h + (size_t)s2 * F1 + c);
        uint2 u3 = *reinterpret_cast<const uint2*>(g_h1h + (size_t)s3 * F1 + c);
        float2 p0a = __half22float2(*reinterpret_cast<__half2*>(&u0.x));
        float2 p0b = __half22float2(*reinterpret_cast<__half2*>(&u0.y));
        float2 p1a = __half22float2(*reinterpret_cast<__half2*>(&u1.x));
        float2 p1b = __half22float2(*reinterpret_cast<__half2*>(&u1.y));
        float2 p2a = __half22float2(*reinterpret_cast<__half2*>(&u2.x));
        float2 p2b = __half22float2(*reinterpret_cast<__half2*>(&u2.y));
        float2 p3a = __half22float2(*reinterpret_cast<__half2*>(&u3.x));
        float2 p3b = __half22float2(*reinterpret_cast<__half2*>(&u3.y));
        acc.x += a0 * p0a.x + a1 * p1a.x + a2 * p2a.x + a3 * p3a.x;
        acc.y += a0 * p0a.y + a1 * p1a.y + a2 * p2a.y + a3 * p3a.y;
        acc.z += a0 * p0b.x + a1 * p1b.x + a2 * p2b.x + a3 * p3b.x;
        acc.w += a0 * p0b.y + a1 * p1b.y + a2 * p2b.y + a3 * p3b.y;
    }
    for (; i < end; i++) {
        int idx = i - beg;
        int s = g_src[i];
        float a;
        if (idx < MAXDEG) a = s_alpha[idx][head];
        else a = expf(leaky(g_as1[s * H1 + head] + adv, 0.2f) - m);
        uint2 u = *reinterpret_cast<const uint2*>(g_h1h + (size_t)s * F1 + c);
        float2 pa = __half22float2(*reinterpret_cast<__half2*>(&u.x));
        float2 pb = __half22float2(*reinterpret_cast<__half2*>(&u.y));
        acc.x += a * pa.x; acc.y += a * pa.y; acc.z += a * pb.x; acc.w += a * pb.y;
    }
    float4 bb = *reinterpret_cast<const float4*>(b1 + c);
    __half2 h01 = __floats2half2_rn(leaky(acc.x * rinv + bb.x, 0.01f),
                                    leaky(acc.y * rinv + bb.y, 0.01f));
    __half2 h23 = __floats2half2_rn(leaky(acc.z * rinv + bb.z, 0.01f),
                                    leaky(acc.w * rinv + bb.w, 0.01f));
    uint2 st;
    st.x = *reinterpret_cast<uint32_t*>(&h01);
    st.y = *reinterpret_cast<uint32_t*>(&h23);
    *reinterpret_cast<uint2*>(g_o1h + (size_t)n * F1 + c) = st;

    // reset CSR counters for next graph replay (last consumer of g_cnt/g_cur)
    if (threadIdx.x == 0) { g_cnt[n] = 0; g_cur[n] = 0; }
}

// ---------------- fused softmax + layer-2 aggregation (bbox only) -----------
__global__ void k_agg2(const void* __restrict__ bbox, const float* __restrict__ b2,
                       float* __restrict__ out) {
    __shared__ float s_alpha[MAXDEG][H2];
    __shared__ float4 red[H2][32];
    int bi = blockIdx.x;
    int head = threadIdx.x >> 5;
    int lane = threadIdx.x & 31;
    int c = head * 128 + lane * 4;
    int n = load_idx(bbox, bi);
    int beg = g_off[n], end = g_off[n + 1];
    int deg = end - beg;
    float adv = g_ad2[n * H2 + head];

    float m = -1e30f;
    for (int i = beg + lane; i < end; i += 32) {
        int s = g_src[i];
        float e = leaky(g_as2[s * H2 + head] + adv, 0.2f);
        int idx = i - beg;
        if (idx < MAXDEG) s_alpha[idx][head] = e;
        m = fmaxf(m, e);
    }
    #pragma unroll
    for (int o = 16; o; o >>= 1) m = fmaxf(m, __shfl_xor_sync(~0u, m, o));
    __syncwarp();

    float sum = 0.f;
    for (int idx = lane; idx < deg; idx += 32) {
        float ex;
        if (idx < MAXDEG) {
            ex = expf(s_alpha[idx][head] - m);
            s_alpha[idx][head] = ex;
        } else {
            int s = g_src[beg + idx];
            ex = expf(leaky(g_as2[s * H2 + head] + adv, 0.2f) - m);
        }
        sum += ex;
    }
    #pragma unroll
    for (int o = 16; o; o >>= 1) sum += __shfl_xor_sync(~0u, sum, o);
    float rinv = 1.f / (sum + 1e-16f);
    __syncwarp();

    float4 acc = make_float4(0.f, 0.f, 0.f, 0.f);
    int e = beg;
    for (; e + 4 <= end && (e - beg) + 4 <= MAXDEG; e += 4) {
        int idx = e - beg;
        int s0 = g_src[e], s1 = g_src[e + 1], s2 = g_src[e + 2], s3 = g_src[e + 3];
        float a0 = s_alpha[idx][head];
        float a1 = s_alpha[idx + 1][head];
        float a2 = s_alpha[idx + 2][head];
        float a3 = s_alpha[idx + 3][head];
        uint2 u0 = *reinterpret_cast<const uint2*>(g_h2h + (size_t)s0 * F2 + c);
        uint2 u1 = *reinterpret_cast<const uint2*>(g_h2h + (size_t)s1 * F2 + c);
        uint2 u2 = *reinterpret_cast<const uint2*>(g_h2h + (size_t)s2 * F2 + c);
        uint2 u3 = *reinterpret_cast<const uint2*>(g_h2h + (size_t)s3 * F2 + c);
        float2 p0a = __half22float2(*reinterpret_cast<__half2*>(&u0.x));
        float2 p0b = __half22float2(*reinterpret_cast<__half2*>(&u0.y));
        float2 p1a = __half22float2(*reinterpret_cast<__half2*>(&u1.x));
        float2 p1b = __half22float2(*reinterpret_cast<__half2*>(&u1.y));
        float2 p2a = __half22float2(*reinterpret_cast<__half2*>(&u2.x));
        float2 p2b = __half22float2(*reinterpret_cast<__half2*>(&u2.y));
        float2 p3a = __half22float2(*reinterpret_cast<__half2*>(&u3.x));
        float2 p3b = __half22float2(*reinterpret_cast<__half2*>(&u3.y));
        acc.x += a0 * p0a.x + a1 * p1a.x + a2 * p2a.x + a3 * p3a.x;
        acc.y += a0 * p0a.y + a1 * p1a.y + a2 * p2a.y + a3 * p3a.y;
        acc.z += a0 * p0b.x + a1 * p1b.x + a2 * p2b.x + a3 * p3b.x;
        acc.w += a0 * p0b.y + a1 * p1b.y + a2 * p2b.y + a3 * p3b.y;
    }
    for (; e < end; e++) {
        int idx = e - beg;
        int s = g_src[e];
        float a;
        if (idx < MAXDEG) a = s_alpha[idx][head];
        else a = expf(leaky(g_as2[s * H2 + head] + adv, 0.2f) - m);
        uint2 u = *reinterpret_cast<const uint2*>(g_h2h + (size_t)s * F2 + c);
        float2 pa = __half22float2(*reinterpret_cast<__half2*>(&u.x));
        float2 pb = __half22float2(*reinterpret_cast<__half2*>(&u.y));
        acc.x += a * pa.x; acc.y += a * pa.y; acc.z += a * pb.x; acc.w += a * pb.y;
    }
    acc.x *= rinv; acc.y *= rinv; acc.z *= rinv; acc.w *= rinv;
    red[head][lane] = acc;
    __syncthreads();
    if (head == 0) {
        float4 r0 = red[0][lane], r1 = red[1][lane], r2 = red[2][lane];
        float4 bb = *reinterpret_cast<const float4*>(b2 + lane * 4);
        float4 o;
        o.x = leaky((r0.x + r1.x + r2.x) * (1.f / 3.f) + bb.x, 0.01f);
        o.y = leaky((r0.y + r1.y + r2.y) * (1.f / 3.f) + bb.y, 0.01f);
        o.z = leaky((r0.z + r1.z + r2.z) * (1.f / 3.f) + bb.z, 0.01f);
        o.w = leaky((r0.w + r1.w + r2.w) * (1.f / 3.f) + bb.w, 0.01f);
        *reinterpret_cast<float4*>(out + (size_t)bi * 128 + lane * 4) = o;
    }
}

// ---------------- launch: fork CSR chain onto a second stream ----------------
extern "C" void kernel_launch(void* const* d_in, const int* in_sizes, int n_in,
                              void* d_out, int out_size) {
    const float *x = nullptr, *W1 = nullptr, *W2 = nullptr, *b1 = nullptr, *b2 = nullptr;
    const float *att_src1 = nullptr, *att_dst1 = nullptr;
    const float *att_src2 = nullptr, *att_dst2 = nullptr;
    const void *ei = nullptr, *bbox = nullptr;
    int n640 = 0, n384 = 0;
    for (int i = 0; i < n_in; i++) {
        switch (in_sizes[i]) {
            case N_NODES * GCN_IN: x    = (const float*)d_in[i]; break;
            case 2 * N_EDGES:      ei   = d_in[i]; break;
            case N_BBOX:           bbox = d_in[i]; break;
            case GCN_IN * F1:      W1   = (const float*)d_in[i]; break;
            case F1 * F2:          W2   = (const float*)d_in[i]; break;
            case C2:               b2   = (const float*)d_in[i]; break;
            case F1:
                if      (n640 == 0) att_src1 = (const float*)d_in[i];
                else if (n640 == 1) att_dst1 = (const float*)d_in[i];
                else                b1       = (const float*)d_in[i];
                n640++; break;
            case F2:
                if (n384 == 0) att_src2 = (const float*)d_in[i];
                else           att_dst2 = (const float*)d_in[i];
                n384++; break;
            default: break;
        }
    }
    float* out = (float*)d_out;

    __half *xh, *w1h, *w2h;
    cudaGetSymbolAddress((void**)&xh,  g_xh);
    cudaGetSymbolAddress((void**)&w1h, g_w1h);
    cudaGetSymbolAddress((void**)&w2h, g_w2h);

    static cudaStream_t s2 = nullptr;
    static cudaEvent_t evFork = nullptr, evJoin = nullptr;
    if (s2 == nullptr) {
        cudaStreamCreateWithFlags(&s2, cudaStreamNonBlocking);
        cudaEventCreateWithFlags(&evFork, cudaEventDisableTiming);
        cudaEventCreateWithFlags(&evJoin, cudaEventDisableTiming);
        cudaFuncSetAttribute(gemm_f16<0>, cudaFuncAttributeMaxDynamicSharedMemorySize, GEMM_SMEM);
        cudaFuncSetAttribute(gemm_f16<1>, cudaFuncAttributeMaxDynamicSharedMemorySize, GEMM_SMEM);
    }

    // fork: CSR chain + W2 transpose on s2, dense chain on default stream
    cudaEventRecord(evFork, 0);
    cudaStreamWaitEvent(s2, evFork, 0);

    k_detect<<<1, 32, 0, s2>>>(ei);
    k_hist<<<(ET + 255) / 256, 256, 0, s2>>>(ei);
    k_scan_fused<<<NB_SCAN, 1024, 0, s2>>>();
    k_scatter<<<(ET + 255) / 256, 256, 0, s2>>>(ei);
    k_transpose_h<<<dim3(F2 / 32, F1 / 32), dim3(32, 8), 0, s2>>>(W2, w2h, F1, F2);
    cudaEventRecord(evJoin, s2);

    k_tohalf<<<(N_NODES * GCN_IN / 8 + 255) / 256, 256>>>(x, xh, N_NODES * GCN_IN / 8);
    k_transpose_h<<<dim3(F1 / 32, GCN_IN / 32), dim3(32, 8)>>>(W1, w1h, GCN_IN, F1);
    {
        dim3 g(F1 / GBN, (N_NODES + GBM - 1) / GBM);
        gemm_f16<0><<<g, 256, GEMM_SMEM>>>(att_src1, att_dst1);
    }

    // join: agg1 needs CSR + gemm1
    cudaStreamWaitEvent(0, evJoin, 0);
    k_agg1<<<N_NODES, H1 * 32>>>(b1);

    {
        dim3 g(F2 / GBN, (N_NODES + GBM - 1) / GBM);
        gemm_f16<1><<<g, 256, GEMM_SMEM>>>(att_src2, att_dst2);
    }
    k_agg2<<<N_BBOX, H2 * 32>>>(bbox, b2, out);
}